// round 5
// baseline (speedup 1.0000x reference)
#include <cuda_runtime.h>
#include <cuda_bf16.h>
#include <cstdint>
#include <math.h>

// Problem constants: N=8, S=8192, C=1, K=1024, V=64
#define NS_TOTAL 65536
#define VDIM 64
#define KCW 1024
#define BM 128
#define EPS 6.0e-3f

// ---- smem layout (bytes) ----
#define SM_EB    0               // [1024][64] bf16 SW128-swizzled (131072)
#define SM_XB    131072          // [128][64] bf16 SW128-swizzled (16384)
#define SM_XF    147456          // [128][65] fp32 padded (33280)
#define SM_EN    180736          // [1024] fp32 (4096)
#define SM_XN    184832          // [128] fp32 (512)
#define SM_RM4   185344          // [4][128] fp32 (2048)
#define SM_THR   187392          // [128] fp32 (512)
#define SM_CNT   187904          // [128] int (512)
#define SM_CAND  188416          // [128][16] u16 (4096)
#define SM_AMIN  192512          // [128] int (512)
#define SM_RSUM  193024          // [128] fp32 (512)
#define SMEM_BYTES 193536

typedef unsigned int uint;

__device__ float g_en[KCW];
__device__ int   g_counts[KCW];
__device__ unsigned long long g_ebf[KCW * VDIM / 4];   // bf16 E, pre-swizzled
__device__ int   g_nflag;
__device__ int   g_flagrows[NS_TOTAL];

// ---------------------------------------------------------------------------
__device__ __forceinline__ uint32_t smem_u32(const void* p) {
    uint32_t a;
    asm("{ .reg .u64 t; cvta.to.shared.u64 t, %1; cvt.u32.u64 %0, t; }" : "=r"(a) : "l"(p));
    return a;
}
__device__ __host__ __forceinline__ int swz128(int off) {
    return off ^ ((off >> 3) & 0x70);
}
__device__ __forceinline__ unsigned long long pack4bf16(float4 f) {
    __nv_bfloat162 a = __floats2bfloat162_rn(f.x, f.y);
    __nv_bfloat162 b = __floats2bfloat162_rn(f.z, f.w);
    uint ua = *reinterpret_cast<uint*>(&a);
    uint ub = *reinterpret_cast<uint*>(&b);
    return (unsigned long long)ua | ((unsigned long long)ub << 32);
}
__device__ __forceinline__ void ldsm_x4(uint* r, uint32_t addr) {
    asm volatile("ldmatrix.sync.aligned.m8n8.x4.shared.b16 {%0,%1,%2,%3}, [%4];"
        : "=r"(r[0]), "=r"(r[1]), "=r"(r[2]), "=r"(r[3]) : "r"(addr));
}
__device__ __forceinline__ void ldsm_x2(uint* r, uint32_t addr) {
    asm volatile("ldmatrix.sync.aligned.m8n8.x2.shared.b16 {%0,%1}, [%2];"
        : "=r"(r[0]), "=r"(r[1]) : "r"(addr));
}
__device__ __forceinline__ void mma_bf16(float* c, const uint* a, const uint* b) {
    asm volatile("mma.sync.aligned.m16n8k16.row.col.f32.bf16.bf16.f32 "
        "{%0,%1,%2,%3}, {%4,%5,%6,%7}, {%8,%9}, {%0,%1,%2,%3};"
        : "+f"(c[0]), "+f"(c[1]), "+f"(c[2]), "+f"(c[3])
        : "r"(a[0]), "r"(a[1]), "r"(a[2]), "r"(a[3]), "r"(b[0]), "r"(b[1]));
}

// ---------------------------------------------------------------------------
// Kernel 1: prep — exact en (sequential mul+add), bf16-swizzled E, zero state
// ---------------------------------------------------------------------------
__global__ void vq_prep_kernel(const float* __restrict__ emb) {
    int k = blockIdx.x * blockDim.x + threadIdx.x;   // 0..1023
    if (k >= KCW) return;
    const float* e = emb + (size_t)k * VDIM;
    float acc = 0.0f;
    #pragma unroll 8
    for (int v = 0; v < VDIM; v++)
        acc = __fadd_rn(acc, __fmul_rn(e[v], e[v]));
    g_en[k]     = acc;
    g_counts[k] = 0;
    if (k == 0) g_nflag = 0;

    const float4* e4 = reinterpret_cast<const float4*>(e);
    char* eb = reinterpret_cast<char*>(g_ebf);
    #pragma unroll
    for (int v4 = 0; v4 < 16; v4++) {
        unsigned long long p = pack4bf16(e4[v4]);
        *reinterpret_cast<unsigned long long*>(eb + swz128(k * 128 + v4 * 8)) = p;
    }
}

// ---------------------------------------------------------------------------
// Kernel 2: HMMA selection (2 sweeps) + exact rescore + outputs.
// grid 512 x 256 threads. 8 warps = 2 row-halves x 4 cw-quarters.
// ---------------------------------------------------------------------------
__global__ __launch_bounds__(256, 1)
void vq_hmma_kernel(const float* __restrict__ x, const float* __restrict__ emb,
                    float* __restrict__ out0, float* __restrict__ out1,
                    float* __restrict__ out2) {
    extern __shared__ char sm[];
    float* xf     = (float*)(sm + SM_XF);
    float* en_s   = (float*)(sm + SM_EN);
    float* xn_s   = (float*)(sm + SM_XN);
    float* rm4    = (float*)(sm + SM_RM4);
    float* thr_s  = (float*)(sm + SM_THR);
    int*   rowcnt = (int*)(sm + SM_CNT);
    unsigned short* cand = (unsigned short*)(sm + SM_CAND);
    int*   amin_s = (int*)(sm + SM_AMIN);
    float* rsum   = (float*)(sm + SM_RSUM);
    const uint32_t sbase = smem_u32(sm);

    const int tid = threadIdx.x;
    const int w   = tid >> 5;
    const int l   = tid & 31;
    const int rg  = w >> 2;              // row half (0: rows 0-63, 1: 64-127)
    const int cg  = w & 3;               // codeword quarter (256 each)
    const int rowbase = rg * 64;
    const int row0 = blockIdx.x * BM;

    // ---- load X tile: fp32 padded + bf16 swizzled ----
    const float4* x4 = reinterpret_cast<const float4*>(x) + (size_t)row0 * (VDIM / 4);
    #pragma unroll
    for (int t = 0; t < 8; t++) {
        int idx = tid + t * 256;         // 2048 float4
        int r   = idx >> 4;
        int v4  = idx & 15;
        float4 f = x4[idx];
        float* d = xf + r * 65 + v4 * 4;
        d[0] = f.x; d[1] = f.y; d[2] = f.z; d[3] = f.w;
        *reinterpret_cast<unsigned long long*>(sm + SM_XB + swz128(r * 128 + v4 * 8)) = pack4bf16(f);
    }
    // ---- load pre-swizzled bf16 E (131072 B) + en ----
    {
        const uint4* eg = reinterpret_cast<const uint4*>(g_ebf);
        uint4* ed = reinterpret_cast<uint4*>(sm + SM_EB);
        #pragma unroll
        for (int t = 0; t < 32; t++) ed[tid + t * 256] = eg[tid + t * 256];
        #pragma unroll
        for (int t = 0; t < 4; t++) en_s[tid + t * 256] = g_en[tid + t * 256];
    }
    __syncthreads();

    // ---- exact xn per row (sequential mul+add, v ascending) ----
    if (tid < BM) {
        float acc = 0.0f;
        const float* xr = xf + tid * 65;
        #pragma unroll 8
        for (int v = 0; v < VDIM; v++)
            acc = __fadd_rn(acc, __fmul_rn(xr[v], xr[v]));
        xn_s[tid] = acc;
    }

    // ---- persistent B fragments: this warp's 64 rows, K=64 (8 n x 4 k x 2 regs) ----
    uint bfr[8][4][2];
    #pragma unroll
    for (int n = 0; n < 8; n++)
        #pragma unroll
        for (int k = 0; k < 4; k++)
            ldsm_x2(bfr[n][k], sbase + SM_XB +
                swz128((rowbase + 8 * n + (l & 7)) * 128 + k * 32 + ((l >> 3) & 1) * 16));

    // =================== sweep 1: per-row min of u = en - 2*dot ===================
    float minn[8][2];
    #pragma unroll
    for (int n = 0; n < 8; n++) { minn[n][0] = 3.402823466e38f; minn[n][1] = 3.402823466e38f; }

    #pragma unroll 1
    for (int c = 0; c < 16; c++) {
        int cwb = cg * 256 + c * 16;
        float acc[8][4];
        #pragma unroll
        for (int n = 0; n < 8; n++)
            #pragma unroll
            for (int j = 0; j < 4; j++) acc[n][j] = 0.0f;
        #pragma unroll
        for (int k = 0; k < 4; k++) {
            uint a4[4];
            ldsm_x4(a4, sbase + SM_EB +
                swz128((cwb + (l & 15)) * 128 + k * 32 + (l >> 4) * 16));
            #pragma unroll
            for (int n = 0; n < 8; n++) mma_bf16(acc[n], a4, bfr[n][k]);
        }
        float en0 = en_s[cwb + (l >> 2)];
        float en1 = en_s[cwb + (l >> 2) + 8];
        #pragma unroll
        for (int n = 0; n < 8; n++) {
            float u0 = fmaf(-2.0f, acc[n][0], en0);
            float u1 = fmaf(-2.0f, acc[n][1], en0);
            float u2 = fmaf(-2.0f, acc[n][2], en1);
            float u3 = fmaf(-2.0f, acc[n][3], en1);
            minn[n][0] = fminf(minn[n][0], fminf(u0, u2));
            minn[n][1] = fminf(minn[n][1], fminf(u1, u3));
        }
    }
    // reduce min across the 8 lanes sharing each row (l/4 varies)
    #pragma unroll
    for (int n = 0; n < 8; n++)
        #pragma unroll
        for (int p = 0; p < 2; p++) {
            float v = minn[n][p];
            v = fminf(v, __shfl_xor_sync(0xffffffffu, v, 4));
            v = fminf(v, __shfl_xor_sync(0xffffffffu, v, 8));
            v = fminf(v, __shfl_xor_sync(0xffffffffu, v, 16));
            minn[n][p] = v;
        }
    if (l < 4) {
        #pragma unroll
        for (int n = 0; n < 8; n++) {
            rm4[cg * 128 + rowbase + 8 * n + 2 * l]     = minn[n][0];
            rm4[cg * 128 + rowbase + 8 * n + 2 * l + 1] = minn[n][1];
        }
    }
    __syncthreads();
    if (tid < BM) {
        float t0 = fminf(fminf(rm4[tid], rm4[128 + tid]),
                         fminf(rm4[256 + tid], rm4[384 + tid]));
        thr_s[tid]  = t0 + EPS;
        rowcnt[tid] = 0;
        rsum[tid]   = 0.0f;
    }
    __syncthreads();

    // =================== sweep 2: collect candidates u <= thr ===================
    float tr[8][2];
    #pragma unroll
    for (int n = 0; n < 8; n++) {
        tr[n][0] = thr_s[rowbase + 8 * n + 2 * (l & 3)];
        tr[n][1] = thr_s[rowbase + 8 * n + 2 * (l & 3) + 1];
    }
    #pragma unroll 1
    for (int c = 0; c < 16; c++) {
        int cwb = cg * 256 + c * 16;
        float acc[8][4];
        #pragma unroll
        for (int n = 0; n < 8; n++)
            #pragma unroll
            for (int j = 0; j < 4; j++) acc[n][j] = 0.0f;
        #pragma unroll
        for (int k = 0; k < 4; k++) {
            uint a4[4];
            ldsm_x4(a4, sbase + SM_EB +
                swz128((cwb + (l & 15)) * 128 + k * 32 + (l >> 4) * 16));
            #pragma unroll
            for (int n = 0; n < 8; n++) mma_bf16(acc[n], a4, bfr[n][k]);
        }
        float en0 = en_s[cwb + (l >> 2)];
        float en1 = en_s[cwb + (l >> 2) + 8];
        int cw0 = cwb + (l >> 2);
        int cw1 = cw0 + 8;
        #pragma unroll
        for (int n = 0; n < 8; n++) {
            int r0 = rowbase + 8 * n + 2 * (l & 3);
            float u0 = fmaf(-2.0f, acc[n][0], en0);
            float u1 = fmaf(-2.0f, acc[n][1], en0);
            float u2 = fmaf(-2.0f, acc[n][2], en1);
            float u3 = fmaf(-2.0f, acc[n][3], en1);
            if (u0 <= tr[n][0]) { int p = atomicAdd(&rowcnt[r0], 1);     if (p < 16) cand[r0 * 16 + p]       = (unsigned short)cw0; }
            if (u2 <= tr[n][0]) { int p = atomicAdd(&rowcnt[r0], 1);     if (p < 16) cand[r0 * 16 + p]       = (unsigned short)cw1; }
            if (u1 <= tr[n][1]) { int p = atomicAdd(&rowcnt[r0 + 1], 1); if (p < 16) cand[(r0 + 1) * 16 + p] = (unsigned short)cw0; }
            if (u3 <= tr[n][1]) { int p = atomicAdd(&rowcnt[r0 + 1], 1); if (p < 16) cand[(r0 + 1) * 16 + p] = (unsigned short)cw1; }
        }
    }
    __syncthreads();

    // ---- exact rescore (thread-per-row, reference rounding, lexicographic min) ----
    if (tid < BM) {
        int cnt = rowcnt[tid];
        if (cnt <= 16) {
            float bv = 3.402823466e38f;
            int   bi = 1 << 30;
            const float* xr = xf + tid * 65;
            float xn = xn_s[tid];
            for (int cI = 0; cI < cnt; cI++) {
                int k = cand[tid * 16 + cI];
                const float* er = emb + (size_t)k * VDIM;
                float acc = 0.0f;
                #pragma unroll 16
                for (int v = 0; v < VDIM; v++)
                    acc = __fmaf_rn(xr[v], er[v], acc);
                float s = __fadd_rn(__fsub_rn(xn, __fmul_rn(2.0f, acc)), en_s[k]);
                if (s < bv || (s == bv && k < bi)) { bv = s; bi = k; }
            }
            amin_s[tid] = bi;
            atomicAdd(&g_counts[bi], 1);
        } else {
            int pos = atomicAdd(&g_nflag, 1);
            g_flagrows[pos] = row0 + tid;
            amin_s[tid] = -1;
        }
    }
    __syncthreads();

    // ---- outputs: out0 = fl(fl(o-x)+x); out1 = out2 = sum (x-o)^2 ----
    #pragma unroll 4
    for (int t = 0; t < 32; t++) {
        int i = t * 256 + tid;           // 8192 elements
        int r = i >> 6;
        int v = i & 63;
        int bi = amin_s[r];
        if (bi >= 0) {
            float o  = emb[(size_t)bi * VDIM + v];
            float xv = xf[r * 65 + v];
            float dd = __fsub_rn(xv, o);
            float sq = __fmul_rn(dd, dd);
            #pragma unroll
            for (int off = 16; off > 0; off >>= 1)
                sq += __shfl_down_sync(0xffffffffu, sq, off);
            if (l == 0) atomicAdd(&rsum[r], sq);   // 2 adds/row: order-invariant
            out0[(size_t)(row0 + r) * VDIM + v] = __fadd_rn(__fsub_rn(o, xv), xv);
        }
    }
    __syncthreads();
    if (tid < BM && amin_s[tid] >= 0) {
        float s = rsum[tid];
        out1[row0 + tid] = s;
        out2[row0 + tid] = s;
    }
}

// ---------------------------------------------------------------------------
// Kernel 3: fallback for shortlist-overflow rows (full exact 1024-scan)
// ---------------------------------------------------------------------------
__global__ void vq_fix_kernel(const float* __restrict__ x, const float* __restrict__ emb,
                              float* __restrict__ out0, float* __restrict__ out1,
                              float* __restrict__ out2) {
    __shared__ float xrow[8][65];
    int nf  = g_nflag;
    int wid = threadIdx.x >> 5;
    int lid = threadIdx.x & 31;
    for (int f = blockIdx.x * 8 + wid; f < nf; f += gridDim.x * 8) {
        int row = g_flagrows[f];
        const float* xr = x + (size_t)row * VDIM;
        xrow[wid][lid]      = xr[lid];
        xrow[wid][lid + 32] = xr[lid + 32];
        __syncwarp();
        float xn = 0.0f;
        #pragma unroll 8
        for (int v = 0; v < VDIM; v++)
            xn = __fadd_rn(xn, __fmul_rn(xrow[wid][v], xrow[wid][v]));
        float bv = 3.402823466e38f;
        int   bi = 1 << 30;
        for (int j = 0; j < 32; j++) {
            int k = j * 32 + lid;
            const float* er = emb + (size_t)k * VDIM;
            float acc = 0.0f;
            #pragma unroll 16
            for (int v = 0; v < VDIM; v++)
                acc = __fmaf_rn(xrow[wid][v], er[v], acc);
            float s = __fadd_rn(__fsub_rn(xn, __fmul_rn(2.0f, acc)), g_en[k]);
            if (s < bv || (s == bv && k < bi)) { bv = s; bi = k; }
        }
        #pragma unroll
        for (int off = 16; off > 0; off >>= 1) {
            float ov = __shfl_down_sync(0xffffffffu, bv, off);
            int   oi = __shfl_down_sync(0xffffffffu, bi, off);
            if (ov < bv || (ov == bv && oi < bi)) { bv = ov; bi = oi; }
        }
        bi = __shfl_sync(0xffffffffu, bi, 0);
        if (lid == 0) atomicAdd(&g_counts[bi], 1);
        float sq = 0.0f;
        #pragma unroll
        for (int h = 0; h < 2; h++) {
            int v = lid + 32 * h;
            float o  = emb[(size_t)bi * VDIM + v];
            float xv = xrow[wid][v];
            float dd = __fsub_rn(xv, o);
            sq += dd * dd;
            out0[(size_t)row * VDIM + v] = __fadd_rn(__fsub_rn(o, xv), xv);
        }
        #pragma unroll
        for (int off = 16; off > 0; off >>= 1)
            sq += __shfl_down_sync(0xffffffffu, sq, off);
        if (lid == 0) { out1[row] = sq; out2[row] = sq; }
        __syncwarp();
    }
}

// ---------------------------------------------------------------------------
// Kernel 4: entropy of the histogram
// ---------------------------------------------------------------------------
__global__ void vq_entropy_kernel(float* __restrict__ ent) {
    __shared__ float warpsum[32];
    int k = threadIdx.x;
    int c = g_counts[k];
    float term = 0.0f;
    if (c > 0) {
        float p = (float)c * (1.0f / 65536.0f);
        term = -p * logf(p);
    }
    #pragma unroll
    for (int off = 16; off > 0; off >>= 1)
        term += __shfl_down_sync(0xffffffffu, term, off);
    int lane = k & 31, wid = k >> 5;
    if (lane == 0) warpsum[wid] = term;
    __syncthreads();
    if (wid == 0) {
        float s = warpsum[lane];
        #pragma unroll
        for (int off = 16; off > 0; off >>= 1)
            s += __shfl_down_sync(0xffffffffu, s, off);
        if (lane == 0) *ent = s;
    }
}

// ---------------------------------------------------------------------------
extern "C" void kernel_launch(void* const* d_in, const int* in_sizes, int n_in,
                              void* d_out, int out_size) {
    const float* x;
    const float* emb;
    if (in_sizes[0] == NS_TOTAL * VDIM) {
        x   = (const float*)d_in[0];
        emb = (const float*)d_in[1];
    } else {
        x   = (const float*)d_in[1];
        emb = (const float*)d_in[0];
    }

    float* out0 = (float*)d_out;
    float* out1 = out0 + (size_t)NS_TOTAL * VDIM;
    float* out2 = out1 + NS_TOTAL;
    float* ent  = out2 + NS_TOTAL;

    cudaFuncSetAttribute(vq_hmma_kernel,
                         cudaFuncAttributeMaxDynamicSharedMemorySize, SMEM_BYTES);

    vq_prep_kernel<<<8, 128>>>(emb);
    vq_hmma_kernel<<<512, 256, SMEM_BYTES>>>(x, emb, out0, out1, out2);
    vq_fix_kernel<<<32, 256>>>(x, emb, out0, out1, out2);
    vq_entropy_kernel<<<1, 1024>>>(ent);
}